// round 14
// baseline (speedup 1.0000x reference)
#include <cuda_runtime.h>
#include <cuda_fp16.h>
#include <math.h>
#include <stdint.h>

#define B_    1024
#define HID   256
#define HGEN  512
#define VOC   5
#define EMBD  64
#define LMAX  100
#define NB    128
#define NTHR  256

#define Y0F_MAT 1048576   // halves per y0 frag matrix (32 kb x 64 mb x 512)

// ---------------- static device scratch (frag layouts: [kb][mb][hi256|lo256]) ----------------
__device__ __align__(16) __half g_y0f[(size_t)2 * LMAX * Y0F_MAT];
__device__ float  g_h1[(size_t)4 * B_ * HID];             // L1 h plain (combine)
__device__ __align__(16) __half g_h1f[4 * 524288];        // [u] 16kb x 64mb x 512
__device__ __align__(16) float  g_tab0i[2 * VOC * 4 * HID];  // L0 token tab, interleaved, bias folded
__device__ __align__(16) float  g_c1bi[2 * 4 * HID];         // c1b interleaved
__device__ __align__(16) float  g_tabg0[VOC * 4 * HGEN];     // gen0 token tab, interleaved, bias folded
__device__ __align__(16) float  g_g1bi[4 * HGEN];            // g1b interleaved
__device__ __align__(16) __half g_h0f [2][1048576];       // ping-pong dec h0 frag
__device__ __align__(16) __half g_h1df[2][1048576];       // ping-pong dec h1 frag
__device__ float  g_h1pl[(size_t)B_ * HGEN];              // plain h1 for logits
// weight frags [kb][nb][hi256|lo256]; ALL gate-interleaved rows (row' = j*4+g)
__device__ __align__(16) __half g_c0Whhf[2 * 524288];
__device__ __align__(16) __half g_c1Wihf[2 * 1048576];
__device__ __align__(16) __half g_c1Whhf[2 * 524288];
__device__ __align__(16) __half g_g0Whhf[2097152];
__device__ __align__(16) __half g_g1Wihf[2097152];
__device__ __align__(16) __half g_g1Whhf[2097152];

// ---------------- software grid barrier ----------------
__device__ unsigned g_cnt;
__device__ volatile unsigned g_gen;

__device__ __forceinline__ void gbar() {
    __syncthreads();
    __threadfence();
    if (threadIdx.x == 0) {
        unsigned gen = g_gen;
        if (atomicAdd(&g_cnt, 1u) == NB - 1u) {
            g_cnt = 0;
            __threadfence();
            g_gen = gen + 1u;
        } else {
            while (g_gen == gen) { }
        }
        __threadfence();
    }
    __syncthreads();
}

// ---------------- frag store helpers ----------------
__device__ __forceinline__ void frag_store(__half* base, int m, int k, float v) {
    int mb = m >> 4, kb = k >> 4, rr = m & 15, cc = k & 15;
    int lane = ((rr & 7) << 2) + ((cc & 7) >> 1);
    int intra = (lane << 3) + (((rr >> 3) + ((cc >> 3) << 1)) << 1) + (cc & 1);
    size_t off = ((size_t)(kb * 64 + mb) << 9) + intra;
    __half hi = __float2half_rn(v);
    base[off] = hi;
    base[off + 256] = __float2half_rn(v - __half2float(hi));
}

__device__ __forceinline__ void wfrag_store(__half* base, int NBc, int n, int k, float v) {
    int nb = n >> 4, kb = k >> 4, nn = n & 15, cc = k & 15;
    int lane = ((nn & 7) << 2) + ((cc & 7) >> 1);
    int intra = (lane << 3) + ((nn >> 3) << 2) + ((cc >> 3) << 1) + (cc & 1);
    size_t off = ((size_t)(kb * NBc + nb) << 9) + intra;
    __half hi = __float2half_rn(v);
    base[off] = hi;
    base[off + 256] = __float2half_rn(v - __half2float(hi));
}

// ---------------- primitives ----------------
__device__ __forceinline__ void mma16816(float* d, uint4 a, uint32_t b0, uint32_t b1) {
    asm volatile(
        "mma.sync.aligned.m16n8k16.row.col.f32.f16.f16.f32 "
        "{%0,%1,%2,%3}, {%4,%5,%6,%7}, {%8,%9}, {%0,%1,%2,%3};"
        : "+f"(d[0]), "+f"(d[1]), "+f"(d[2]), "+f"(d[3])
        : "r"(a.x), "r"(a.y), "r"(a.z), "r"(a.w), "r"(b0), "r"(b1));
}
__device__ __forceinline__ uint4 lds128(uint32_t a) {
    uint4 r;
    asm volatile("ld.shared.v4.u32 {%0,%1,%2,%3}, [%4];"
                 : "=r"(r.x), "=r"(r.y), "=r"(r.z), "=r"(r.w) : "r"(a));
    return r;
}
__device__ __forceinline__ uint32_t smem_u32(const void* p) {
    uint32_t a;
    asm("{ .reg .u64 t; cvta.to.shared.u64 t, %1; cvt.u32.u64 %0, t; }" : "=r"(a) : "l"(p));
    return a;
}
__device__ __forceinline__ void bulk_cp(uint32_t dst, const void* src, uint32_t mbar) {
    asm volatile(
        "cp.async.bulk.shared::cta.global.mbarrier::complete_tx::bytes [%0], [%1], 8192, [%2];"
        :: "r"(dst), "l"(src), "r"(mbar) : "memory");
}
__device__ __forceinline__ void waitp(uint32_t mbar, int phase) {
    asm volatile(
        "{\n\t"
        ".reg .pred P1;\n\t"
        "WAIT_LOOP_%=:\n\t"
        "mbarrier.try_wait.parity.acquire.cta.shared::cta.b64 P1, [%0], %1, 0x989680;\n\t"
        "@P1 bra.uni WAIT_DONE_%=;\n\t"
        "bra.uni WAIT_LOOP_%=;\n\t"
        "WAIT_DONE_%=:\n\t"
        "}"
        :: "r"(mbar), "r"(phase) : "memory");
}
__device__ __forceinline__ float lds32(uint32_t a) {
    float v;
    asm volatile("ld.shared.f32 %0, [%1];" : "=f"(v) : "r"(a));
    return v;
}
__device__ __forceinline__ void sts32(uint32_t a, float v) {
    asm volatile("st.shared.f32 [%0], %1;" :: "r"(a), "f"(v));
}

#define OFF_MBAR  0
#define OFF_TILES 1024
#define OFF_CST   (OFF_TILES + 131072)
#define SMEM_SZ   (OFF_CST + 2 * 16 * NTHR * 4)

struct GOp {
    const __half* a; int aKbOff;
    const __half* w; int wNB;
    int nkb;          // k16 blocks (always even)
};

__device__ __forceinline__ void issue_stage(
    int sg, int st, const GOp& o0, const GOp& o1,
    int mtile, int ntile, uint32_t smb, int tid)
{
    if (tid != 0) return;
    int k0 = 2 * st;
    const GOp& op = (k0 < o0.nkb) ? o0 : o1;
    int local0 = (k0 < o0.nkb) ? k0 : k0 - o0.nkb;
    uint32_t sbase = smb + OFF_TILES + (uint32_t)(sg & 3) * 32768u;
    uint32_t mbar = smb + OFF_MBAR + (uint32_t)(sg & 3) * 8u;
    asm volatile("mbarrier.arrive.expect_tx.shared.b64 _, [%0], %1;"
                 :: "r"(mbar), "r"(32768u) : "memory");
    #pragma unroll
    for (int q = 0; q < 2; q++) {
        int local = local0 + q;
        int akb = op.aKbOff + local;
        const __half* asrc = op.a + ((size_t)(akb * 64 + mtile * 8) << 9);
        const __half* wsrc = op.w + ((size_t)(local * op.wNB + ntile * 8) << 9);
        bulk_cp(sbase + q * 8192u, asrc, mbar);
        bulk_cp(sbase + 16384u + q * 8192u, wsrc, mbar);
    }
}

__device__ __forceinline__ void prefetch3(
    int cnt, const GOp& o0, const GOp& o1, int mt, int nt, uint32_t smb, int tid)
{
    int nst = (o0.nkb + o1.nkb) >> 1;
    int n = nst < 3 ? nst : 3;
    for (int st = 0; st < n; st++)
        issue_stage(cnt + st, st, o0, o1, mt, nt, smb, tid);
}

__device__ __forceinline__ void mma_mainloop(
    const GOp& o0, const GOp& o1, int mtile, int ntile,
    uint32_t smb, int& cnt, float (&acc)[2][8][4], int nPre)
{
    const int tid = threadIdx.x, w = tid >> 5, lane = tid & 31;
    #pragma unroll
    for (int i = 0; i < 2; i++)
        #pragma unroll
        for (int na = 0; na < 8; na++)
            #pragma unroll
            for (int q = 0; q < 4; q++) acc[i][na][q] = 0.f;

    const int nstages = (o0.nkb + o1.nkb) >> 1;
    for (int st = nPre; st < 3 && st < nstages; st++)
        issue_stage(cnt + st, st, o0, o1, mtile, ntile, smb, tid);

    const int ma = (w & 3) * 2;
    const int nj = (w >> 2) * 4;

    for (int st = 0; st < nstages; st++) {
        int sg = cnt + st;
        waitp(smb + OFF_MBAR + (uint32_t)(sg & 3) * 8u, (sg >> 2) & 1);
        uint32_t sbase = smb + OFF_TILES + (uint32_t)(sg & 3) * 32768u + lane * 16;

        #pragma unroll
        for (int q = 0; q < 2; q++) {
            uint32_t laA = sbase + q * 8192u;
            uint32_t laB = sbase + 16384u + q * 8192u;
            uint4 ah0 = lds128(laA + (ma + 0) * 1024);
            uint4 al0 = lds128(laA + (ma + 0) * 1024 + 512);
            uint4 ah1 = lds128(laA + (ma + 1) * 1024);
            uint4 al1 = lds128(laA + (ma + 1) * 1024 + 512);
            uint4 bh[4], bl[4];
            #pragma unroll
            for (int j = 0; j < 4; j++) {
                bh[j] = lds128(laB + (nj + j) * 1024);
                bl[j] = lds128(laB + (nj + j) * 1024 + 512);
            }
            #pragma unroll
            for (int j = 0; j < 4; j++) {
                mma16816(acc[0][2*j],   ah0, bh[j].x, bh[j].y);
                mma16816(acc[1][2*j],   ah1, bh[j].x, bh[j].y);
                mma16816(acc[0][2*j+1], ah0, bh[j].z, bh[j].w);
                mma16816(acc[1][2*j+1], ah1, bh[j].z, bh[j].w);
            }
            #pragma unroll
            for (int j = 0; j < 4; j++) {
                mma16816(acc[0][2*j],   ah0, bl[j].x, bl[j].y);
                mma16816(acc[1][2*j],   ah1, bl[j].x, bl[j].y);
                mma16816(acc[0][2*j+1], ah0, bl[j].z, bl[j].w);
                mma16816(acc[1][2*j+1], ah1, bl[j].z, bl[j].w);
            }
            #pragma unroll
            for (int j = 0; j < 4; j++) {
                mma16816(acc[0][2*j],   al0, bh[j].x, bh[j].y);
                mma16816(acc[1][2*j],   al1, bh[j].x, bh[j].y);
                mma16816(acc[0][2*j+1], al0, bh[j].z, bh[j].w);
                mma16816(acc[1][2*j+1], al1, bh[j].z, bh[j].w);
            }
        }
        __syncthreads();
        if (st + 3 < nstages)
            issue_stage(cnt + st + 3, st + 3, o0, o1, mtile, ntile, smb, tid);
    }
    cnt += nstages;
}

__device__ __forceinline__ float sigf(float x) { return 1.f / (1.f + expf(-x)); }

// ---- decoder epilogue: register c-state; tok indexed row&127 (block-local smem) ----
__device__ void mma_tile_lstm_reg(const GOp& o0, const GOp& o1,
                                  int mtile, int ntile, uint32_t smb, int& cnt,
                                  const float* __restrict__ tab, const int* __restrict__ tok,
                                  float* cstate, __half* hfrag, float* hplain, int nPre)
{
    float acc[2][8][4];
    mma_mainloop(o0, o1, mtile, ntile, smb, cnt, acc, nPre);
    const int tid = threadIdx.x, w = tid >> 5, lane = tid & 31;
    const int ma = (w & 3) * 2;
    const int nab = (w >> 2) * 8;
    #pragma unroll
    for (int i = 0; i < 2; i++) {
        int rbase = mtile * 128 + (ma + i) * 16 + (lane >> 2);
        #pragma unroll
        for (int na = 0; na < 8; na++) {
            float x0 = __shfl_xor_sync(0xffffffffu, acc[i][na][0], 1);
            float x1 = __shfl_xor_sync(0xffffffffu, acc[i][na][1], 1);
            float x2 = __shfl_xor_sync(0xffffffffu, acc[i][na][2], 1);
            float x3 = __shfl_xor_sync(0xffffffffu, acc[i][na][3], 1);
            int c0col = ntile * 128 + (nab + na) * 8 + (lane & 3) * 2;
            int j = c0col >> 2;
            float zi, zf, zg, zo;
            int row;
            if ((lane & 1) == 0) {
                row = rbase;
                zi = acc[i][na][0]; zf = acc[i][na][1]; zg = x0; zo = x1;
            } else {
                row = rbase + 8;
                zg = acc[i][na][2]; zo = acc[i][na][3]; zi = x2; zf = x3;
            }
            float4 tv;
            if (tok) {
                int v = tok[row & 127];
                tv = *reinterpret_cast<const float4*>(tab + ((size_t)v * (4 * HGEN) + j * 4));
            } else {
                tv = *reinterpret_cast<const float4*>(tab + j * 4);
            }
            zi += tv.x; zf += tv.y; zg += tv.z; zo += tv.w;
            int ci = i * 8 + na;
            float c = sigf(zf) * cstate[ci] + sigf(zi) * tanhf(zg);
            cstate[ci] = c;
            float h = sigf(zo) * tanhf(c);
            frag_store(hfrag, row, j, h);
            if (hplain) hplain[(size_t)row * HGEN + j] = h;
        }
    }
}

// ---- encoder epilogue: smem c-state (round-12 proven) ----
__device__ void mma_tile_lstm_smem(const GOp& o0, const GOp& o1,
                                   int mtile, int ntile, uint32_t smb, int& cnt,
                                   const float* __restrict__ tab, int tabStride,
                                   const int* __restrict__ tok, int tokStride,
                                   uint32_t csbase, int first,
                                   __half* hfrag, int kOff,
                                   float* hplain, int hplStride)
{
    float acc[2][8][4];
    mma_mainloop(o0, o1, mtile, ntile, smb, cnt, acc, 0);
    const int tid = threadIdx.x, w = tid >> 5, lane = tid & 31;
    const int ma = (w & 3) * 2;
    const int nab = (w >> 2) * 8;
    #pragma unroll
    for (int i = 0; i < 2; i++) {
        int rbase = mtile * 128 + (ma + i) * 16 + (lane >> 2);
        #pragma unroll
        for (int na = 0; na < 8; na++) {
            float x0 = __shfl_xor_sync(0xffffffffu, acc[i][na][0], 1);
            float x1 = __shfl_xor_sync(0xffffffffu, acc[i][na][1], 1);
            float x2 = __shfl_xor_sync(0xffffffffu, acc[i][na][2], 1);
            float x3 = __shfl_xor_sync(0xffffffffu, acc[i][na][3], 1);
            int c0col = ntile * 128 + (nab + na) * 8 + (lane & 3) * 2;
            int j = c0col >> 2;
            float zi, zf, zg, zo;
            int row;
            if ((lane & 1) == 0) {
                row = rbase;
                zi = acc[i][na][0]; zf = acc[i][na][1]; zg = x0; zo = x1;
            } else {
                row = rbase + 8;
                zg = acc[i][na][2]; zo = acc[i][na][3]; zi = x2; zf = x3;
            }
            float4 tv;
            if (tok) {
                int v = tok[row * tokStride];
                tv = *reinterpret_cast<const float4*>(tab + ((size_t)v * tabStride + j * 4));
            } else {
                tv = *reinterpret_cast<const float4*>(tab + j * 4);
            }
            zi += tv.x; zf += tv.y; zg += tv.z; zo += tv.w;
            int ci = i * 8 + na;
            uint32_t ca = csbase + (uint32_t)(ci * NTHR + tid) * 4u;
            float cprev = first ? 0.f : lds32(ca);
            float c = sigf(zf) * cprev + sigf(zi) * tanhf(zg);
            sts32(ca, c);
            float h = sigf(zo) * tanhf(c);
            frag_store(hfrag, row, kOff + j, h);
            if (hplain) hplain[(size_t)row * hplStride + j] = h;
        }
    }
}

__device__ __forceinline__ void pipe_init(uint32_t smb) {
    if (threadIdx.x == 0) {
        #pragma unroll
        for (int s = 0; s < 4; s++)
            asm volatile("mbarrier.init.shared.b64 [%0], 1;"
                         :: "r"(smb + OFF_MBAR + s * 8u) : "memory");
    }
    __syncthreads();
}

// ---------------- setup ----------------
__global__ void setup_kernel(const float* __restrict__ emb,
                             const float* __restrict__ c0Wih,
                             const float* __restrict__ c0Whh,
                             const float* __restrict__ c0b,
                             const float* __restrict__ c1Wih,
                             const float* __restrict__ c1Whh,
                             const float* __restrict__ c1b,
                             const float* __restrict__ g0Wih,
                             const float* __restrict__ g0Whh,
                             const float* __restrict__ g0b,
                             const float* __restrict__ g1Wih,
                             const float* __restrict__ g1Whh,
                             const float* __restrict__ g1b) {
    int idx = blockIdx.x * blockDim.x + threadIdx.x;
    int stride = gridDim.x * blockDim.x;

    for (int i = idx; i < 2 * VOC * 4 * HID; i += stride) {
        int rp = i % (4 * HID);
        int v = (i / (4 * HID)) % VOC;
        int d = i / (4 * HID * VOC);
        int n = (rp & 3) * HID + (rp >> 2);
        const float* e = emb + v * EMBD;
        const float* ww = c0Wih + ((size_t)d * 4 * HID + n) * EMBD;
        float s = 0.f;
        #pragma unroll
        for (int k = 0; k < EMBD; k++) s += e[k] * ww[k];
        g_tab0i[i] = s + c0b[d * 4 * HID + n];
    }
    for (int i = idx; i < 2 * 4 * HID; i += stride) {
        int rp = i % (4 * HID), d = i / (4 * HID);
        g_c1bi[i] = c1b[d * 4 * HID + (rp & 3) * HID + (rp >> 2)];
    }
    for (int i = idx; i < VOC * 4 * HGEN; i += stride) {
        int rp = i % (4 * HGEN);
        int v = i / (4 * HGEN);
        int n = (rp & 3) * HGEN + (rp >> 2);
        const float* e = emb + v * EMBD;
        const float* ww = g0Wih + (size_t)n * EMBD;
        float s = 0.f;
        #pragma unroll
        for (int k = 0; k < EMBD; k++) s += e[k] * ww[k];
        g_tabg0[i] = s + g0b[n];
    }
    for (int i = idx; i < 4 * HGEN; i += stride)
        g_g1bi[i] = g1b[(i & 3) * HGEN + (i >> 2)];

    for (int i = idx; i < 2 * 1024 * 256; i += stride) {
        int d = i / (1024 * 256), r = i % (1024 * 256);
        int rp = r / 256, k = r % 256;
        int n = (rp & 3) * HID + (rp >> 2);
        wfrag_store(g_c0Whhf + d * 524288, 64, rp, k, c0Whh[(size_t)d * 1024 * 256 + (size_t)n * 256 + k]);
    }
    for (int i = idx; i < 2 * 1024 * 512; i += stride) {
        int d = i / (1024 * 512), r = i % (1024 * 512);
        int rp = r / 512, k = r % 512;
        int n = (rp & 3) * HID + (rp >> 2);
        wfrag_store(g_c1Wihf + d * 1048576, 64, rp, k, c1Wih[(size_t)d * 1024 * 512 + (size_t)n * 512 + k]);
    }
    for (int i = idx; i < 2 * 1024 * 256; i += stride) {
        int d = i / (1024 * 256), r = i % (1024 * 256);
        int rp = r / 256, k = r % 256;
        int n = (rp & 3) * HID + (rp >> 2);
        wfrag_store(g_c1Whhf + d * 524288, 64, rp, k, c1Whh[(size_t)d * 1024 * 256 + (size_t)n * 256 + k]);
    }
    for (int i = idx; i < 2048 * 512; i += stride) {
        int rp = i / 512, k = i % 512;
        int n = (rp & 3) * HGEN + (rp >> 2);
        wfrag_store(g_g0Whhf, 128, rp, k, g0Whh[(size_t)n * 512 + k]);
    }
    for (int i = idx; i < 2048 * 512; i += stride) {
        int rp = i / 512, k = i % 512;
        int n = (rp & 3) * HGEN + (rp >> 2);
        wfrag_store(g_g1Wihf, 128, rp, k, g1Wih[(size_t)n * 512 + k]);
    }
    for (int i = idx; i < 2048 * 512; i += stride) {
        int rp = i / 512, k = i % 512;
        int n = (rp & 3) * HGEN + (rp >> 2);
        wfrag_store(g_g1Whhf, 128, rp, k, g1Whh[(size_t)n * 512 + k]);
    }
}

// ---------------- encoder: round-12 proven (fused, SMEM c-state, 1 gbar/step) ----------------
__global__ __launch_bounds__(NTHR, 1) void encoder_kernel(
    const int* __restrict__ leftC, const int* __restrict__ rightC, int L)
{
    extern __shared__ char sm[];
    const uint32_t smb = smem_u32(sm);
    const int bid = blockIdx.x, tid = threadIdx.x;
    pipe_init(smb);
    int cnt = 0;

    for (int t = 0; t < L; t++) {
        #pragma unroll
        for (int ti = 0; ti < 2; ti++) {
            int tile = bid + ti * 128;
            int u = tile >> 6, rem = tile & 63;
            int mt = rem >> 3, nt = rem & 7;
            int seq = u >> 1, dir = u & 1;
            int time = dir ? (L - 1 - t) : t;
            GOp o0, o1 = { nullptr, 0, nullptr, 0, 0 };
            if (t > 0) {
                int ptime = dir ? (time + 1) : (time - 1);
                o0 = { g_y0f + (size_t)(seq * LMAX + ptime) * Y0F_MAT, dir * 16,
                       g_c0Whhf + dir * 524288, 64, 16 };
            } else {
                o0 = { nullptr, 0, nullptr, 0, 0 };
            }
            const int* ctx = seq ? rightC : leftC;
            mma_tile_lstm_smem(o0, o1, mt, nt, smb, cnt,
                               g_tab0i + dir * VOC * (4 * HID), 4 * HID,
                               ctx + time, L,
                               smb + OFF_CST + (uint32_t)ti * 16 * NTHR * 4, t == 0,
                               g_y0f + (size_t)(seq * LMAX + time) * Y0F_MAT, dir * HID,
                               nullptr, 0);
        }
        gbar();
    }

    for (int s = 0; s < L; s++) {
        #pragma unroll
        for (int ti = 0; ti < 2; ti++) {
            if (ti == 1 && s > 0) continue;
            int tile = bid + ti * 128;
            int u = tile >> 6, rem = tile & 63;
            int mt = rem >> 3, nt = rem & 7;
            int seq = (u == 0 || u == 2) ? 0 : 1;
            int dir = (u == 1 || u == 2) ? 1 : 0;
            int time = dir ? (L - 1 - s) : s;
            GOp o0 = { g_y0f + (size_t)(seq * LMAX + time) * Y0F_MAT, 0,
                       g_c1Wihf + dir * 1048576, 64, 32 };
            GOp o1;
            if (s) o1 = { g_h1f + u * 524288, 0, g_c1Whhf + dir * 524288, 64, 16 };
            else   o1 = { nullptr, 0, nullptr, 0, 0 };
            mma_tile_lstm_smem(o0, o1, mt, nt, smb, cnt,
                               g_c1bi + dir * (4 * HID), 0, nullptr, 0,
                               smb + OFF_CST + (uint32_t)ti * 16 * NTHR * 4, s == 0,
                               g_h1f + u * 524288, 0,
                               g_h1 + (size_t)u * B_ * HID, HID);
        }
        gbar();
    }

    for (int idx = bid * NTHR + tid; idx < B_ * HGEN; idx += NB * NTHR) {
        int b = idx / HGEN, j = idx % HGEN;
        float lf, rf;
        if (j < HID) {
            lf = g_h1[((size_t)0 * B_ + b) * HID + j];
            rf = g_h1[((size_t)3 * B_ + b) * HID + j];
        } else {
            int jj = j - HID;
            lf = g_h1[((size_t)2 * B_ + b) * HID + jj];
            rf = g_h1[((size_t)1 * B_ + b) * HID + jj];
        }
        float v = 0.5f * (lf + rf);
        frag_store(g_h0f[0],  b, j, v);
        frag_store(g_h1df[0], b, j, v);
    }
}

// ---------------- decoder: 2 gbars/step; logits overlapped into phase A ----------------
__global__ __launch_bounds__(NTHR, 1) void decoder_kernel(
    const float* __restrict__ outW, const float* __restrict__ outb,
    float* __restrict__ out, int T)
{
    extern __shared__ char sm[];
    const uint32_t smb = smem_u32(sm);
    int* sTok = reinterpret_cast<int*>(sm + OFF_CST);     // [128]
    const int bid = blockIdx.x, tid = threadIdx.x;
    const int mt = bid >> 4, nt = bid & 15;
    const int w = tid >> 5, lane = tid & 31;
    pipe_init(smb);
    int cnt = 0;
    float c0reg[16], c1reg[16];
    #pragma unroll
    for (int i = 0; i < 16; i++) { c0reg[i] = 0.f; c1reg[i] = 0.f; }

    GOp onull = { nullptr, 0, nullptr, 0, 0 };
    for (int t = 0; t < T; t++) {
        const int p = t & 1;
        // ---- phase A: kick off stage fetches, overlap logits(t-1)+argmax, then GEMM+pw0 ----
        GOp oA = { g_h0f[p], 0, g_g0Whhf, 128, 32 };
        prefetch3(cnt, oA, onull, mt, nt, smb, tid);
        if (t == 0) {
            for (int i = tid; i < 128; i += NTHR) sTok[i] = 0;
        } else {
            // logits for this block's epilogue rows (mt*128..+127); h1pl synced by post-B gbar
            for (int rr = 0; rr < 16; rr++) {
                int row = mt * 128 + w * 16 + rr;
                const float* h = g_h1pl + (size_t)row * HGEN;
                float a0 = 0.f, a1 = 0.f, a2 = 0.f, a3 = 0.f, a4 = 0.f;
                for (int k = lane; k < HGEN; k += 32) {
                    float hv = h[k];
                    a0 += hv * outW[0 * HGEN + k];
                    a1 += hv * outW[1 * HGEN + k];
                    a2 += hv * outW[2 * HGEN + k];
                    a3 += hv * outW[3 * HGEN + k];
                    a4 += hv * outW[4 * HGEN + k];
                }
                #pragma unroll
                for (int off = 16; off; off >>= 1) {
                    a0 += __shfl_down_sync(0xffffffffu, a0, off);
                    a1 += __shfl_down_sync(0xffffffffu, a1, off);
                    a2 += __shfl_down_sync(0xffffffffu, a2, off);
                    a3 += __shfl_down_sync(0xffffffffu, a3, off);
                    a4 += __shfl_down_sync(0xffffffffu, a4, off);
                }
                if (lane == 0) {
                    float L0 = a0 + outb[0], L1 = a1 + outb[1], L2 = a2 + outb[2],
                          L3 = a3 + outb[3], L4 = a4 + outb[4];
                    int bi = 0; float best = L0;
                    if (L1 > best) { best = L1; bi = 1; }
                    if (L2 > best) { best = L2; bi = 2; }
                    if (L3 > best) { best = L3; bi = 3; }
                    if (L4 > best) { best = L4; bi = 4; }
                    sTok[w * 16 + rr] = bi;
                    if (nt == 0) {
                        float* op = out + ((size_t)row * T + (t - 1)) * VOC;
                        op[0] = L0; op[1] = L1; op[2] = L2; op[3] = L3; op[4] = L4;
                    }
                }
            }
        }
        __syncthreads();      // sTok visible before epilogue (mainloop syncs also follow)
        mma_tile_lstm_reg(oA, onull, mt, nt, smb, cnt, g_tabg0, sTok, c0reg,
                          g_h0f[p ^ 1], nullptr, 3);
        gbar();
        // ---- phase B: gen1 GEMM + fused pw1 ----
        {
            GOp o0 = { g_h0f[p ^ 1], 0, g_g1Wihf, 128, 32 };
            GOp o1 = { g_h1df[p], 0, g_g1Whhf, 128, 32 };
            mma_tile_lstm_reg(o0, o1, mt, nt, smb, cnt, g_g1bi, nullptr, c1reg,
                              g_h1df[p ^ 1], g_h1pl, 0);
        }
        gbar();
    }

    // ---- tail: logits for t = T-1 (output only; nt==0 blocks) ----
    if (nt == 0) {
        for (int rr = 0; rr < 16; rr++) {
            int row = mt * 128 + w * 16 + rr;
            const float* h = g_h1pl + (size_t)row * HGEN;
            float a0 = 0.f, a1 = 0.f, a2 = 0.f, a3 = 0.f, a4 = 0.f;
            for (int k = lane; k < HGEN; k += 32) {
                float hv = h[k];
                a0 += hv * outW[0 * HGEN + k];
                a1 += hv * outW[1 * HGEN + k];
                a2 += hv * outW[2 * HGEN + k];
                a3 += hv * outW[3 * HGEN + k];
                a4 += hv * outW[4 * HGEN + k];
            }
            #pragma unroll
            for (int off = 16; off; off >>= 1) {
                a0 += __shfl_down_sync(0xffffffffu, a0, off);
                a1 += __shfl_down_sync(0xffffffffu, a1, off);
                a2 += __shfl_down_sync(0xffffffffu, a2, off);
                a3 += __shfl_down_sync(0xffffffffu, a3, off);
                a4 += __shfl_down_sync(0xffffffffu, a4, off);
            }
            if (lane == 0) {
                float* op = out + ((size_t)row * T + (T - 1)) * VOC;
                op[0] = a0 + outb[0]; op[1] = a1 + outb[1]; op[2] = a2 + outb[2];
                op[3] = a3 + outb[3]; op[4] = a4 + outb[4];
            }
        }
    }
}

// ---------------- orchestration ----------------
extern "C" void kernel_launch(void* const* d_in, const int* in_sizes, int n_in,
                              void* d_out, int out_size) {
    int ei = (in_sizes[2] == 1) ? 3 : 2;
    const int*   leftC  = (const int*)d_in[0];
    const int*   rightC = (const int*)d_in[1];
    const float* emb    = (const float*)d_in[ei + 0];
    const float* c0Wih  = (const float*)d_in[ei + 1];
    const float* c0Whh  = (const float*)d_in[ei + 2];
    const float* c0b    = (const float*)d_in[ei + 3];
    const float* c1Wih  = (const float*)d_in[ei + 4];
    const float* c1Whh  = (const float*)d_in[ei + 5];
    const float* c1b    = (const float*)d_in[ei + 6];
    const float* g0Wih  = (const float*)d_in[ei + 7];
    const float* g0Whh  = (const float*)d_in[ei + 8];
    const float* g0b    = (const float*)d_in[ei + 9];
    const float* g1Wih  = (const float*)d_in[ei + 10];
    const float* g1Whh  = (const float*)d_in[ei + 11];
    const float* g1b    = (const float*)d_in[ei + 12];
    const float* outW   = (const float*)d_in[ei + 13];
    const float* outb   = (const float*)d_in[ei + 14];
    float* out = (float*)d_out;

    const int L = in_sizes[0] / B_;       // 100
    const int T = out_size / (B_ * VOC);  // 256

    cudaFuncSetAttribute(encoder_kernel, cudaFuncAttributeMaxDynamicSharedMemorySize, SMEM_SZ);
    cudaFuncSetAttribute(decoder_kernel, cudaFuncAttributeMaxDynamicSharedMemorySize, SMEM_SZ);

    setup_kernel<<<512, 256>>>(emb, c0Wih, c0Whh, c0b, c1Wih, c1Whh, c1b,
                               g0Wih, g0Whh, g0b, g1Wih, g1Whh, g1b);
    encoder_kernel<<<NB, NTHR, SMEM_SZ>>>(leftC, rightC, L);
    decoder_kernel<<<NB, NTHR, SMEM_SZ>>>(outW, outb, out, T);
}

// round 15
// speedup vs baseline: 1.1804x; 1.1804x over previous
#include <cuda_runtime.h>
#include <cuda_fp16.h>
#include <math.h>
#include <stdint.h>

#define B_    1024
#define HID   256
#define HGEN  512
#define VOC   5
#define EMBD  64
#define LMAX  100
#define NB    128
#define NTHR  256

#define Y0F_MAT 1048576   // halves per y0 frag matrix (32 kb x 64 mb x 512)

// ---------------- static device scratch (frag layouts: [kb][mb][hi256|lo256]) ----------------
__device__ __align__(16) __half g_y0f[(size_t)2 * LMAX * Y0F_MAT];
__device__ float  g_h1[(size_t)4 * B_ * HID];             // L1 h plain (combine)
__device__ __align__(16) __half g_h1f[4 * 524288];        // [u] 16kb x 64mb x 512
__device__ __align__(16) float  g_tab0i[2 * VOC * 4 * HID];  // L0 token tab, interleaved, bias folded
__device__ __align__(16) float  g_c1bi[2 * 4 * HID];         // c1b interleaved
__device__ __align__(16) float  g_tabg0[VOC * 4 * HGEN];     // gen0 token tab, interleaved, bias folded
__device__ __align__(16) float  g_g1bi[4 * HGEN];            // g1b interleaved
__device__ __align__(16) __half g_h0f [2][1048576];       // ping-pong dec h0 frag
__device__ __align__(16) __half g_h1df[2][1048576];       // ping-pong dec h1 frag
__device__ float  g_h1pl[(size_t)B_ * HGEN];              // plain h1 for logits
__device__ int    g_tok[B_];
// weight frags [kb][nb][hi256|lo256]; ALL gate-interleaved rows (row' = j*4+g)
__device__ __align__(16) __half g_c0Whhf[2 * 524288];
__device__ __align__(16) __half g_c1Wihf[2 * 1048576];
__device__ __align__(16) __half g_c1Whhf[2 * 524288];
__device__ __align__(16) __half g_g0Whhf[2097152];
__device__ __align__(16) __half g_g1Wihf[2097152];
__device__ __align__(16) __half g_g1Whhf[2097152];

// ---------------- software grid barrier ----------------
__device__ unsigned g_cnt;
__device__ volatile unsigned g_gen;

__device__ __forceinline__ void gbar() {
    __syncthreads();
    __threadfence();
    if (threadIdx.x == 0) {
        unsigned gen = g_gen;
        if (atomicAdd(&g_cnt, 1u) == NB - 1u) {
            g_cnt = 0;
            __threadfence();
            g_gen = gen + 1u;
        } else {
            while (g_gen == gen) { }
        }
        __threadfence();
    }
    __syncthreads();
}

// ---------------- frag store helpers ----------------
__device__ __forceinline__ void frag_store(__half* base, int m, int k, float v) {
    int mb = m >> 4, kb = k >> 4, rr = m & 15, cc = k & 15;
    int lane = ((rr & 7) << 2) + ((cc & 7) >> 1);
    int intra = (lane << 3) + (((rr >> 3) + ((cc >> 3) << 1)) << 1) + (cc & 1);
    size_t off = ((size_t)(kb * 64 + mb) << 9) + intra;
    __half hi = __float2half_rn(v);
    base[off] = hi;
    base[off + 256] = __float2half_rn(v - __half2float(hi));
}

__device__ __forceinline__ void wfrag_store(__half* base, int NBc, int n, int k, float v) {
    int nb = n >> 4, kb = k >> 4, nn = n & 15, cc = k & 15;
    int lane = ((nn & 7) << 2) + ((cc & 7) >> 1);
    int intra = (lane << 3) + ((nn >> 3) << 2) + ((cc >> 3) << 1) + (cc & 1);
    size_t off = ((size_t)(kb * NBc + nb) << 9) + intra;
    __half hi = __float2half_rn(v);
    base[off] = hi;
    base[off + 256] = __float2half_rn(v - __half2float(hi));
}

// ---------------- primitives ----------------
__device__ __forceinline__ void mma16816(float* d, uint4 a, uint32_t b0, uint32_t b1) {
    asm volatile(
        "mma.sync.aligned.m16n8k16.row.col.f32.f16.f16.f32 "
        "{%0,%1,%2,%3}, {%4,%5,%6,%7}, {%8,%9}, {%0,%1,%2,%3};"
        : "+f"(d[0]), "+f"(d[1]), "+f"(d[2]), "+f"(d[3])
        : "r"(a.x), "r"(a.y), "r"(a.z), "r"(a.w), "r"(b0), "r"(b1));
}
__device__ __forceinline__ uint4 lds128(uint32_t a) {
    uint4 r;
    asm volatile("ld.shared.v4.u32 {%0,%1,%2,%3}, [%4];"
                 : "=r"(r.x), "=r"(r.y), "=r"(r.z), "=r"(r.w) : "r"(a));
    return r;
}
__device__ __forceinline__ uint32_t smem_u32(const void* p) {
    uint32_t a;
    asm("{ .reg .u64 t; cvta.to.shared.u64 t, %1; cvt.u32.u64 %0, t; }" : "=r"(a) : "l"(p));
    return a;
}
__device__ __forceinline__ void bulk_cp(uint32_t dst, const void* src, uint32_t mbar) {
    asm volatile(
        "cp.async.bulk.shared::cta.global.mbarrier::complete_tx::bytes [%0], [%1], 8192, [%2];"
        :: "r"(dst), "l"(src), "r"(mbar) : "memory");
}
__device__ __forceinline__ void waitp(uint32_t mbar, int phase) {
    asm volatile(
        "{\n\t"
        ".reg .pred P1;\n\t"
        "WAIT_LOOP_%=:\n\t"
        "mbarrier.try_wait.parity.acquire.cta.shared::cta.b64 P1, [%0], %1, 0x989680;\n\t"
        "@P1 bra.uni WAIT_DONE_%=;\n\t"
        "bra.uni WAIT_LOOP_%=;\n\t"
        "WAIT_DONE_%=:\n\t"
        "}"
        :: "r"(mbar), "r"(phase) : "memory");
}
__device__ __forceinline__ float lds32(uint32_t a) {
    float v;
    asm volatile("ld.shared.f32 %0, [%1];" : "=f"(v) : "r"(a));
    return v;
}
__device__ __forceinline__ void sts32(uint32_t a, float v) {
    asm volatile("st.shared.f32 [%0], %1;" :: "r"(a), "f"(v));
}

#define OFF_MBAR  0
#define OFF_TILES 1024
#define OFF_CST   (OFF_TILES + 131072)
#define SMEM_SZ   (OFF_CST + 2 * 16 * NTHR * 4)

struct GOp {
    const __half* a; int aKbOff;
    const __half* w; int wNB;
    int nkb;          // k16 blocks (always even)
};

__device__ __forceinline__ void issue_stage(
    int sg, int st, const GOp& o0, const GOp& o1,
    int mtile, int ntile, uint32_t smb, int tid)
{
    if (tid != 0) return;
    int k0 = 2 * st;
    const GOp& op = (k0 < o0.nkb) ? o0 : o1;
    int local0 = (k0 < o0.nkb) ? k0 : k0 - o0.nkb;
    uint32_t sbase = smb + OFF_TILES + (uint32_t)(sg & 3) * 32768u;
    uint32_t mbar = smb + OFF_MBAR + (uint32_t)(sg & 3) * 8u;
    asm volatile("mbarrier.arrive.expect_tx.shared.b64 _, [%0], %1;"
                 :: "r"(mbar), "r"(32768u) : "memory");
    #pragma unroll
    for (int q = 0; q < 2; q++) {
        int local = local0 + q;
        int akb = op.aKbOff + local;
        const __half* asrc = op.a + ((size_t)(akb * 64 + mtile * 8) << 9);
        const __half* wsrc = op.w + ((size_t)(local * op.wNB + ntile * 8) << 9);
        bulk_cp(sbase + q * 8192u, asrc, mbar);
        bulk_cp(sbase + 16384u + q * 8192u, wsrc, mbar);
    }
}

__device__ __forceinline__ void mma_mainloop(
    const GOp& o0, const GOp& o1, int mtile, int ntile,
    uint32_t smb, int& cnt, float (&acc)[2][8][4])
{
    const int tid = threadIdx.x, w = tid >> 5, lane = tid & 31;
    #pragma unroll
    for (int i = 0; i < 2; i++)
        #pragma unroll
        for (int na = 0; na < 8; na++)
            #pragma unroll
            for (int q = 0; q < 4; q++) acc[i][na][q] = 0.f;

    const int nstages = (o0.nkb + o1.nkb) >> 1;
    if (nstages > 0) issue_stage(cnt + 0, 0, o0, o1, mtile, ntile, smb, tid);
    if (nstages > 1) issue_stage(cnt + 1, 1, o0, o1, mtile, ntile, smb, tid);
    if (nstages > 2) issue_stage(cnt + 2, 2, o0, o1, mtile, ntile, smb, tid);

    const int ma = (w & 3) * 2;
    const int nj = (w >> 2) * 4;

    for (int st = 0; st < nstages; st++) {
        int sg = cnt + st;
        waitp(smb + OFF_MBAR + (uint32_t)(sg & 3) * 8u, (sg >> 2) & 1);
        uint32_t sbase = smb + OFF_TILES + (uint32_t)(sg & 3) * 32768u + lane * 16;

        #pragma unroll
        for (int q = 0; q < 2; q++) {
            uint32_t laA = sbase + q * 8192u;
            uint32_t laB = sbase + 16384u + q * 8192u;
            uint4 ah0 = lds128(laA + (ma + 0) * 1024);
            uint4 al0 = lds128(laA + (ma + 0) * 1024 + 512);
            uint4 ah1 = lds128(laA + (ma + 1) * 1024);
            uint4 al1 = lds128(laA + (ma + 1) * 1024 + 512);
            uint4 bh[4], bl[4];
            #pragma unroll
            for (int j = 0; j < 4; j++) {
                bh[j] = lds128(laB + (nj + j) * 1024);
                bl[j] = lds128(laB + (nj + j) * 1024 + 512);
            }
            #pragma unroll
            for (int j = 0; j < 4; j++) {
                mma16816(acc[0][2*j],   ah0, bh[j].x, bh[j].y);
                mma16816(acc[1][2*j],   ah1, bh[j].x, bh[j].y);
                mma16816(acc[0][2*j+1], ah0, bh[j].z, bh[j].w);
                mma16816(acc[1][2*j+1], ah1, bh[j].z, bh[j].w);
            }
            #pragma unroll
            for (int j = 0; j < 4; j++) {
                mma16816(acc[0][2*j],   ah0, bl[j].x, bl[j].y);
                mma16816(acc[1][2*j],   ah1, bl[j].x, bl[j].y);
                mma16816(acc[0][2*j+1], ah0, bl[j].z, bl[j].w);
                mma16816(acc[1][2*j+1], ah1, bl[j].z, bl[j].w);
            }
            #pragma unroll
            for (int j = 0; j < 4; j++) {
                mma16816(acc[0][2*j],   al0, bh[j].x, bh[j].y);
                mma16816(acc[1][2*j],   al1, bh[j].x, bh[j].y);
                mma16816(acc[0][2*j+1], al0, bh[j].z, bh[j].w);
                mma16816(acc[1][2*j+1], al1, bh[j].z, bh[j].w);
            }
        }
        __syncthreads();
        if (st + 3 < nstages)
            issue_stage(cnt + st + 3, st + 3, o0, o1, mtile, ntile, smb, tid);
    }
    cnt += nstages;
}

__device__ __forceinline__ float sigf(float x) { return 1.f / (1.f + expf(-x)); }

// ---- decoder epilogue: register c-state ----
__device__ void mma_tile_lstm_reg(const GOp& o0, const GOp& o1,
                                  int mtile, int ntile, uint32_t smb, int& cnt,
                                  const float* __restrict__ tab, const int* __restrict__ tok,
                                  float* cstate, __half* hfrag, float* hplain)
{
    float acc[2][8][4];
    mma_mainloop(o0, o1, mtile, ntile, smb, cnt, acc);
    const int tid = threadIdx.x, w = tid >> 5, lane = tid & 31;
    const int ma = (w & 3) * 2;
    const int nab = (w >> 2) * 8;
    #pragma unroll
    for (int i = 0; i < 2; i++) {
        int rbase = mtile * 128 + (ma + i) * 16 + (lane >> 2);
        #pragma unroll
        for (int na = 0; na < 8; na++) {
            float x0 = __shfl_xor_sync(0xffffffffu, acc[i][na][0], 1);
            float x1 = __shfl_xor_sync(0xffffffffu, acc[i][na][1], 1);
            float x2 = __shfl_xor_sync(0xffffffffu, acc[i][na][2], 1);
            float x3 = __shfl_xor_sync(0xffffffffu, acc[i][na][3], 1);
            int c0col = ntile * 128 + (nab + na) * 8 + (lane & 3) * 2;
            int j = c0col >> 2;
            float zi, zf, zg, zo;
            int row;
            if ((lane & 1) == 0) {
                row = rbase;
                zi = acc[i][na][0]; zf = acc[i][na][1]; zg = x0; zo = x1;
            } else {
                row = rbase + 8;
                zg = acc[i][na][2]; zo = acc[i][na][3]; zi = x2; zf = x3;
            }
            float4 tv;
            if (tok) {
                int v = tok[row];
                tv = *reinterpret_cast<const float4*>(tab + ((size_t)v * (4 * HGEN) + j * 4));
            } else {
                tv = *reinterpret_cast<const float4*>(tab + j * 4);
            }
            zi += tv.x; zf += tv.y; zg += tv.z; zo += tv.w;
            int ci = i * 8 + na;
            float c = sigf(zf) * cstate[ci] + sigf(zi) * tanhf(zg);
            cstate[ci] = c;
            float h = sigf(zo) * tanhf(c);
            frag_store(hfrag, row, j, h);
            if (hplain) hplain[(size_t)row * HGEN + j] = h;
        }
    }
}

// ---- encoder epilogue: smem c-state (cs[ci*NTHR+tid]), first flag ----
__device__ void mma_tile_lstm_smem(const GOp& o0, const GOp& o1,
                                   int mtile, int ntile, uint32_t smb, int& cnt,
                                   const float* __restrict__ tab, int tabStride,
                                   const int* __restrict__ tok, int tokStride,
                                   uint32_t csbase, int first,
                                   __half* hfrag, int kOff,
                                   float* hplain, int hplStride)
{
    float acc[2][8][4];
    mma_mainloop(o0, o1, mtile, ntile, smb, cnt, acc);
    const int tid = threadIdx.x, w = tid >> 5, lane = tid & 31;
    const int ma = (w & 3) * 2;
    const int nab = (w >> 2) * 8;
    #pragma unroll
    for (int i = 0; i < 2; i++) {
        int rbase = mtile * 128 + (ma + i) * 16 + (lane >> 2);
        #pragma unroll
        for (int na = 0; na < 8; na++) {
            float x0 = __shfl_xor_sync(0xffffffffu, acc[i][na][0], 1);
            float x1 = __shfl_xor_sync(0xffffffffu, acc[i][na][1], 1);
            float x2 = __shfl_xor_sync(0xffffffffu, acc[i][na][2], 1);
            float x3 = __shfl_xor_sync(0xffffffffu, acc[i][na][3], 1);
            int c0col = ntile * 128 + (nab + na) * 8 + (lane & 3) * 2;
            int j = c0col >> 2;
            float zi, zf, zg, zo;
            int row;
            if ((lane & 1) == 0) {
                row = rbase;
                zi = acc[i][na][0]; zf = acc[i][na][1]; zg = x0; zo = x1;
            } else {
                row = rbase + 8;
                zg = acc[i][na][2]; zo = acc[i][na][3]; zi = x2; zf = x3;
            }
            float4 tv;
            if (tok) {
                int v = tok[row * tokStride];
                tv = *reinterpret_cast<const float4*>(tab + ((size_t)v * tabStride + j * 4));
            } else {
                tv = *reinterpret_cast<const float4*>(tab + j * 4);
            }
            zi += tv.x; zf += tv.y; zg += tv.z; zo += tv.w;
            int ci = i * 8 + na;
            uint32_t ca = csbase + (uint32_t)(ci * NTHR + tid) * 4u;
            float cprev = first ? 0.f : lds32(ca);
            float c = sigf(zf) * cprev + sigf(zi) * tanhf(zg);
            sts32(ca, c);
            float h = sigf(zo) * tanhf(c);
            frag_store(hfrag, row, kOff + j, h);
            if (hplain) hplain[(size_t)row * hplStride + j] = h;
        }
    }
}

__device__ __forceinline__ void pipe_init(uint32_t smb) {
    if (threadIdx.x == 0) {
        #pragma unroll
        for (int s = 0; s < 4; s++)
            asm volatile("mbarrier.init.shared.b64 [%0], 1;"
                         :: "r"(smb + OFF_MBAR + s * 8u) : "memory");
    }
    __syncthreads();
}

// ---------------- setup ----------------
__global__ void setup_kernel(const float* __restrict__ emb,
                             const float* __restrict__ c0Wih,
                             const float* __restrict__ c0Whh,
                             const float* __restrict__ c0b,
                             const float* __restrict__ c1Wih,
                             const float* __restrict__ c1Whh,
                             const float* __restrict__ c1b,
                             const float* __restrict__ g0Wih,
                             const float* __restrict__ g0Whh,
                             const float* __restrict__ g0b,
                             const float* __restrict__ g1Wih,
                             const float* __restrict__ g1Whh,
                             const float* __restrict__ g1b) {
    int idx = blockIdx.x * blockDim.x + threadIdx.x;
    int stride = gridDim.x * blockDim.x;
    for (int i = idx; i < B_; i += stride) g_tok[i] = 0;

    for (int i = idx; i < 2 * VOC * 4 * HID; i += stride) {
        int rp = i % (4 * HID);
        int v = (i / (4 * HID)) % VOC;
        int d = i / (4 * HID * VOC);
        int n = (rp & 3) * HID + (rp >> 2);
        const float* e = emb + v * EMBD;
        const float* ww = c0Wih + ((size_t)d * 4 * HID + n) * EMBD;
        float s = 0.f;
        #pragma unroll
        for (int k = 0; k < EMBD; k++) s += e[k] * ww[k];
        g_tab0i[i] = s + c0b[d * 4 * HID + n];
    }
    for (int i = idx; i < 2 * 4 * HID; i += stride) {
        int rp = i % (4 * HID), d = i / (4 * HID);
        g_c1bi[i] = c1b[d * 4 * HID + (rp & 3) * HID + (rp >> 2)];
    }
    for (int i = idx; i < VOC * 4 * HGEN; i += stride) {
        int rp = i % (4 * HGEN);
        int v = i / (4 * HGEN);
        int n = (rp & 3) * HGEN + (rp >> 2);
        const float* e = emb + v * EMBD;
        const float* ww = g0Wih + (size_t)n * EMBD;
        float s = 0.f;
        #pragma unroll
        for (int k = 0; k < EMBD; k++) s += e[k] * ww[k];
        g_tabg0[i] = s + g0b[n];
    }
    for (int i = idx; i < 4 * HGEN; i += stride)
        g_g1bi[i] = g1b[(i & 3) * HGEN + (i >> 2)];

    for (int i = idx; i < 2 * 1024 * 256; i += stride) {
        int d = i / (1024 * 256), r = i % (1024 * 256);
        int rp = r / 256, k = r % 256;
        int n = (rp & 3) * HID + (rp >> 2);
        wfrag_store(g_c0Whhf + d * 524288, 64, rp, k, c0Whh[(size_t)d * 1024 * 256 + (size_t)n * 256 + k]);
    }
    for (int i = idx; i < 2 * 1024 * 512; i += stride) {
        int d = i / (1024 * 512), r = i % (1024 * 512);
        int rp = r / 512, k = r % 512;
        int n = (rp & 3) * HID + (rp >> 2);
        wfrag_store(g_c1Wihf + d * 1048576, 64, rp, k, c1Wih[(size_t)d * 1024 * 512 + (size_t)n * 512 + k]);
    }
    for (int i = idx; i < 2 * 1024 * 256; i += stride) {
        int d = i / (1024 * 256), r = i % (1024 * 256);
        int rp = r / 256, k = r % 256;
        int n = (rp & 3) * HID + (rp >> 2);
        wfrag_store(g_c1Whhf + d * 524288, 64, rp, k, c1Whh[(size_t)d * 1024 * 256 + (size_t)n * 256 + k]);
    }
    for (int i = idx; i < 2048 * 512; i += stride) {
        int rp = i / 512, k = i % 512;
        int n = (rp & 3) * HGEN + (rp >> 2);
        wfrag_store(g_g0Whhf, 128, rp, k, g0Whh[(size_t)n * 512 + k]);
    }
    for (int i = idx; i < 2048 * 512; i += stride) {
        int rp = i / 512, k = i % 512;
        int n = (rp & 3) * HGEN + (rp >> 2);
        wfrag_store(g_g1Wihf, 128, rp, k, g1Wih[(size_t)n * 512 + k]);
    }
    for (int i = idx; i < 2048 * 512; i += stride) {
        int rp = i / 512, k = i % 512;
        int n = (rp & 3) * HGEN + (rp >> 2);
        wfrag_store(g_g1Whhf, 128, rp, k, g1Whh[(size_t)n * 512 + k]);
    }
}

// ---------------- encoder: fused, SMEM c-state, 1 gbar/step ----------------
__global__ __launch_bounds__(NTHR, 1) void encoder_kernel(
    const int* __restrict__ leftC, const int* __restrict__ rightC, int L)
{
    extern __shared__ char sm[];
    const uint32_t smb = smem_u32(sm);
    const int bid = blockIdx.x, tid = threadIdx.x;
    pipe_init(smb);
    int cnt = 0;

    // -------- layer 0: tiles bid (ti=0) and bid+128 (ti=1) --------
    for (int t = 0; t < L; t++) {
        #pragma unroll
        for (int ti = 0; ti < 2; ti++) {
            int tile = bid + ti * 128;
            int u = tile >> 6, rem = tile & 63;
            int mt = rem >> 3, nt = rem & 7;
            int seq = u >> 1, dir = u & 1;
            int time = dir ? (L - 1 - t) : t;
            GOp o0, o1 = { nullptr, 0, nullptr, 0, 0 };
            if (t > 0) {
                int ptime = dir ? (time + 1) : (time - 1);
                o0 = { g_y0f + (size_t)(seq * LMAX + ptime) * Y0F_MAT, dir * 16,
                       g_c0Whhf + dir * 524288, 64, 16 };
            } else {
                o0 = { nullptr, 0, nullptr, 0, 0 };
            }
            const int* ctx = seq ? rightC : leftC;
            mma_tile_lstm_smem(o0, o1, mt, nt, smb, cnt,
                               g_tab0i + dir * VOC * (4 * HID), 4 * HID,
                               ctx + time, L,
                               smb + OFF_CST + (uint32_t)ti * 16 * NTHR * 4, t == 0,
                               g_y0f + (size_t)(seq * LMAX + time) * Y0F_MAT, dir * HID,
                               nullptr, 0);
        }
        gbar();
    }

    // -------- layer 1: tile bid every step; tile bid+128 only at s=0 --------
    for (int s = 0; s < L; s++) {
        #pragma unroll
        for (int ti = 0; ti < 2; ti++) {
            if (ti == 1 && s > 0) continue;
            int tile = bid + ti * 128;
            int u = tile >> 6, rem = tile & 63;
            int mt = rem >> 3, nt = rem & 7;
            int seq = (u == 0 || u == 2) ? 0 : 1;
            int dir = (u == 1 || u == 2) ? 1 : 0;
            int time = dir ? (L - 1 - s) : s;
            GOp o0 = { g_y0f + (size_t)(seq * LMAX + time) * Y0F_MAT, 0,
                       g_c1Wihf + dir * 1048576, 64, 32 };
            GOp o1;
            if (s) o1 = { g_h1f + u * 524288, 0, g_c1Whhf + dir * 524288, 64, 16 };
            else   o1 = { nullptr, 0, nullptr, 0, 0 };
            mma_tile_lstm_smem(o0, o1, mt, nt, smb, cnt,
                               g_c1bi + dir * (4 * HID), 0, nullptr, 0,
                               smb + OFF_CST + (uint32_t)ti * 16 * NTHR * 4, s == 0,
                               g_h1f + u * 524288, 0,
                               g_h1 + (size_t)u * B_ * HID, HID);
        }
        gbar();
    }

    // -------- combine -> decoder initial h frag (buffer 0) --------
    for (int idx = bid * NTHR + tid; idx < B_ * HGEN; idx += NB * NTHR) {
        int b = idx / HGEN, j = idx % HGEN;
        float lf, rf;
        if (j < HID) {
            lf = g_h1[((size_t)0 * B_ + b) * HID + j];
            rf = g_h1[((size_t)3 * B_ + b) * HID + j];
        } else {
            int jj = j - HID;
            lf = g_h1[((size_t)2 * B_ + b) * HID + jj];
            rf = g_h1[((size_t)1 * B_ + b) * HID + jj];
        }
        float v = 0.5f * (lf + rf);
        frag_store(g_h0f[0],  b, j, v);
        frag_store(g_h1df[0], b, j, v);
    }
}

// ---------------- decoder: 3 gbars/step, reg c-state ----------------
__global__ __launch_bounds__(NTHR, 1) void decoder_kernel(
    const float* __restrict__ outW, const float* __restrict__ outb,
    float* __restrict__ out, int T)
{
    extern __shared__ char sm[];
    const uint32_t smb = smem_u32(sm);
    const int bid = blockIdx.x, tid = threadIdx.x;
    const int mt = bid >> 4, nt = bid & 15;
    pipe_init(smb);
    int cnt = 0;
    float c0reg[16], c1reg[16];
    #pragma unroll
    for (int i = 0; i < 16; i++) { c0reg[i] = 0.f; c1reg[i] = 0.f; }

    for (int t = 0; t < T; t++) {
        const int p = t & 1;
        {   // phase A: gen0 GEMM + fused pw0
            GOp o0 = { g_h0f[p], 0, g_g0Whhf, 128, 32 };
            GOp o1 = { nullptr, 0, nullptr, 0, 0 };
            mma_tile_lstm_reg(o0, o1, mt, nt, smb, cnt, g_tabg0, g_tok, c0reg,
                              g_h0f[p ^ 1], nullptr);
        }
        gbar();
        {   // phase B: gen1 GEMM + fused pw1
            GOp o0 = { g_h0f[p ^ 1], 0, g_g1Wihf, 128, 32 };
            GOp o1 = { g_h1df[p], 0, g_g1Whhf, 128, 32 };
            mma_tile_lstm_reg(o0, o1, mt, nt, smb, cnt, g_g1bi, nullptr, c1reg,
                              g_h1df[p ^ 1], g_h1pl);
        }
        gbar();
        {   // phase C: logits + argmax, 8 warps -> 8 rows
            int w = tid >> 5, lane = tid & 31;
            int row = bid * 8 + w;
            const float* h = g_h1pl + (size_t)row * HGEN;
            float a0 = 0.f, a1 = 0.f, a2 = 0.f, a3 = 0.f, a4 = 0.f;
            for (int k = lane; k < HGEN; k += 32) {
                float hv = h[k];
                a0 += hv * outW[0 * HGEN + k];
                a1 += hv * outW[1 * HGEN + k];
                a2 += hv * outW[2 * HGEN + k];
                a3 += hv * outW[3 * HGEN + k];
                a4 += hv * outW[4 * HGEN + k];
            }
            #pragma unroll
            for (int off = 16; off; off >>= 1) {
                a0 += __shfl_down_sync(0xffffffffu, a0, off);
                a1 += __shfl_down_sync(0xffffffffu, a1, off);
                a2 += __shfl_down_sync(0xffffffffu, a2, off);
                a3 += __shfl_down_sync(0xffffffffu, a3, off);
                a4 += __shfl_down_sync(0xffffffffu, a4, off);
            }
            if (lane == 0) {
                float L0 = a0 + outb[0], L1 = a1 + outb[1], L2 = a2 + outb[2],
                      L3 = a3 + outb[3], L4 = a4 + outb[4];
                float* op = out + ((size_t)row * T + t) * VOC;
                op[0] = L0; op[1] = L1; op[2] = L2; op[3] = L3; op[4] = L4;
                int bi = 0; float best = L0;
                if (L1 > best) { best = L1; bi = 1; }
                if (L2 > best) { best = L2; bi = 2; }
                if (L3 > best) { best = L3; bi = 3; }
                if (L4 > best) { best = L4; bi = 4; }
                g_tok[row] = bi;
            }
        }
        gbar();
    }
}

// ---------------- orchestration ----------------
extern "C" void kernel_launch(void* const* d_in, const int* in_sizes, int n_in,
                              void* d_out, int out_size) {
    int ei = (in_sizes[2] == 1) ? 3 : 2;
    const int*   leftC  = (const int*)d_in[0];
    const int*   rightC = (const int*)d_in[1];
    const float* emb    = (const float*)d_in[ei + 0];
    const float* c0Wih  = (const float*)d_in[ei + 1];
    const float* c0Whh  = (const float*)d_in[ei + 2];
    const float* c0b    = (const float*)d_in[ei + 3];
    const float* c1Wih  = (const float*)d_in[ei + 4];
    const float* c1Whh  = (const float*)d_in[ei + 5];
    const float* c1b    = (const float*)d_in[ei + 6];
    const float* g0Wih  = (const float*)d_in[ei + 7];
    const float* g0Whh  = (const float*)d_in[ei + 8];
    const float* g0b    = (const float*)d_in[ei + 9];
    const float* g1Wih  = (const float*)d_in[ei + 10];
    const float* g1Whh  = (const float*)d_in[ei + 11];
    const float* g1b    = (const float*)d_in[ei + 12];
    const float* outW   = (const float*)d_in[ei + 13];
    const float* outb   = (const float*)d_in[ei + 14];
    float* out = (float*)d_out;

    const int L = in_sizes[0] / B_;       // 100
    const int T = out_size / (B_ * VOC);  // 256

    cudaFuncSetAttribute(encoder_kernel, cudaFuncAttributeMaxDynamicSharedMemorySize, SMEM_SZ);
    cudaFuncSetAttribute(decoder_kernel, cudaFuncAttributeMaxDynamicSharedMemorySize, SMEM_SZ);

    setup_kernel<<<512, 256>>>(emb, c0Wih, c0Whh, c0b, c1Wih, c1Whh, c1b,
                               g0Wih, g0Whh, g0b, g1Wih, g1Whh, g1b);
    encoder_kernel<<<NB, NTHR, SMEM_SZ>>>(leftC, rightC, L);
    decoder_kernel<<<NB, NTHR, SMEM_SZ>>>(outW, outb, out, T);
}